// round 5
// baseline (speedup 1.0000x reference)
#include <cuda_runtime.h>
#include <cstdint>
#include <cstddef>

// ---------------------------------------------------------------------------
// Problem constants (fixed instance)
// ---------------------------------------------------------------------------
#define NBOND_MAX 160001
#define NATOM_MAX 80000
#define HID       448
#define HID4      (HID/4)     // 112 float4 per row

// ---------------------------------------------------------------------------
// Device scratch (allocation-free rule: __device__ globals)
// ---------------------------------------------------------------------------
__device__ float g_binput[(size_t)NBOND_MAX * HID];
__device__ float g_msgA  [(size_t)NBOND_MAX * HID];
__device__ float g_msgB  [(size_t)NBOND_MAX * HID];
__device__ float g_nei   [(size_t)NBOND_MAX * HID];
__device__ float g_atomh [(size_t)NATOM_MAX * HID];

__device__ int   g_bgraph[(size_t)NBOND_MAX * 6];
__device__ int   g_agraph[(size_t)NATOM_MAX * 6];
__device__ int   g_mol   [(size_t)NATOM_MAX];
__device__ int   g_is64;

// ---------------------------------------------------------------------------
// Index dtype detection + normalization.
// If source is int64 (values < 2^31), every odd 32-bit word is 0.
// If source is int32 random bond indices, odd words are the indices themselves
// (P[all 256 odd words == 0] ~ 0).
// ---------------------------------------------------------------------------
__global__ void detect_idx64(const unsigned int* __restrict__ words, int nwords)
{
    if (threadIdx.x == 0 && blockIdx.x == 0) {
        int is64 = 1;
        for (int i = 1; i < nwords; i += 2)
            if (words[i] != 0u) { is64 = 0; break; }
        g_is64 = is64;
    }
}

__global__ void norm_idx(const void* __restrict__ src, int* __restrict__ dst, int n)
{
    int i = blockIdx.x * blockDim.x + threadIdx.x;
    if (i >= n) return;
    if (g_is64) dst[i] = (int)((const long long*)src)[i];
    else        dst[i] = ((const int*)src)[i];
}

// ---------------------------------------------------------------------------
// 3xTF32 GEMM: C[M x 448] = A[M x K] @ W[K x 448]  (+addrow)(+bias)(relu)
// Block tile 128x64x32, 256 threads, warp tile 32x32 (2x4 m16n8k8 mma tiles).
// A/W values split into (tf32_hi, tf32_lo) pairs stored as float2 in smem.
// ---------------------------------------------------------------------------
#define BM 128
#define BN 64
#define BK 32
#define PADA 4   // float2 row stride BK+4 = 36
#define PADB 4   // float2 row stride BN+4 = 68

__device__ __forceinline__ void mma_tf32(float* d, const uint32_t* a, const uint32_t* b) {
    asm volatile(
        "mma.sync.aligned.m16n8k8.row.col.f32.tf32.tf32.f32 "
        "{%0,%1,%2,%3}, {%4,%5,%6,%7}, {%8,%9}, {%0,%1,%2,%3};\n"
        : "+f"(d[0]), "+f"(d[1]), "+f"(d[2]), "+f"(d[3])
        : "r"(a[0]), "r"(a[1]), "r"(a[2]), "r"(a[3]), "r"(b[0]), "r"(b[1]));
}

__device__ __forceinline__ float2 split_tf32(float v) {
    uint32_t hi;
    asm("cvt.rna.tf32.f32 %0, %1;" : "=r"(hi) : "f"(v));
    float hif = __uint_as_float(hi);
    float rest = v - hif;
    uint32_t lo;
    asm("cvt.rna.tf32.f32 %0, %1;" : "=r"(lo) : "f"(rest));
    return make_float2(hif, __uint_as_float(lo));
}

template<bool RELU, bool HAS_ADD, bool HAS_BIAS, bool STORE_RAW>
__global__ void __launch_bounds__(256)
gemm3xtf32(const float* __restrict__ A, int lda,
           const float* __restrict__ W,                 // [K x 448], ldb = 448
           const float* __restrict__ addrow,            // [M x 448] or null
           const float* __restrict__ bias,              // [448] or null
           float* __restrict__ out,                     // [M x 448]
           float* __restrict__ out2,                    // raw (pre-relu) store
           int M, int K)
{
    extern __shared__ float2 sm[];
    float2* sA = sm;                       // [BM][BK+PADA]
    float2* sB = sm + BM * (BK + PADA);    // [BK][BN+PADB]

    const int tid  = threadIdx.x;
    const int m0   = blockIdx.y * BM;
    const int n0   = blockIdx.x * BN;
    const int warp = tid >> 5, lane = tid & 31;
    const int wm   = (warp & 3) * 32;      // 4 warps along M
    const int wn   = (warp >> 2) * 32;     // 2 warps along N
    const int g    = lane >> 2, tig = lane & 3;

    float acc[2][4][4] = {};

    const int nk = (K + BK - 1) / BK;
    for (int kt = 0; kt < nk; ++kt) {
        const int k0 = kt * BK;
        // --- load A tile: 128x32 floats, 16 per thread, coalesced ---
        #pragma unroll
        for (int i = 0; i < 16; ++i) {
            int idx = tid + i * 256;
            int r = idx >> 5, c = idx & 31;
            float v = 0.f;
            int gr = m0 + r, gc = k0 + c;
            if (gr < M && gc < K) v = __ldg(&A[(size_t)gr * lda + gc]);
            sA[r * (BK + PADA) + c] = split_tf32(v);
        }
        // --- load W tile: 32x64 floats, 8 per thread, coalesced ---
        #pragma unroll
        for (int i = 0; i < 8; ++i) {
            int idx = tid + i * 256;
            int r = idx >> 6, c = idx & 63;
            float v = 0.f;
            int gr = k0 + r;
            if (gr < K) v = __ldg(&W[(size_t)gr * HID + n0 + c]);
            sB[r * (BN + PADB) + c] = split_tf32(v);
        }
        __syncthreads();

        #pragma unroll
        for (int kk = 0; kk < BK; kk += 8) {
            uint32_t ah[2][4], al[2][4], bh[4][2], bl[4][2];
            #pragma unroll
            for (int tm = 0; tm < 2; ++tm) {
                int rbase = wm + tm * 16;
                #pragma unroll
                for (int q = 0; q < 4; ++q) {
                    int r = rbase + g + (q & 1) * 8;
                    int c = kk + tig + (q >> 1) * 4;
                    float2 hv = sA[r * (BK + PADA) + c];
                    ah[tm][q] = __float_as_uint(hv.x);
                    al[tm][q] = __float_as_uint(hv.y);
                }
            }
            #pragma unroll
            for (int tn = 0; tn < 4; ++tn) {
                int cbase = wn + tn * 8;
                #pragma unroll
                for (int q = 0; q < 2; ++q) {
                    int r = kk + tig + q * 4;
                    float2 hv = sB[r * (BN + PADB) + cbase + g];
                    bh[tn][q] = __float_as_uint(hv.x);
                    bl[tn][q] = __float_as_uint(hv.y);
                }
            }
            #pragma unroll
            for (int tm = 0; tm < 2; ++tm)
                #pragma unroll
                for (int tn = 0; tn < 4; ++tn) {
                    mma_tf32(acc[tm][tn], ah[tm], bh[tn]);
                    mma_tf32(acc[tm][tn], ah[tm], bl[tn]);
                    mma_tf32(acc[tm][tn], al[tm], bh[tn]);
                }
        }
        __syncthreads();
    }

    // --- epilogue: c0..c3 per mma tile; (c0,c1)/(c2,c3) are col pairs ---
    #pragma unroll
    for (int tm = 0; tm < 2; ++tm) {
        #pragma unroll
        for (int half = 0; half < 2; ++half) {
            int row = m0 + wm + tm * 16 + g + half * 8;
            if (row >= M) continue;
            #pragma unroll
            for (int tn = 0; tn < 4; ++tn) {
                int col = n0 + wn + tn * 8 + 2 * tig;
                float v0 = acc[tm][tn][half * 2 + 0];
                float v1 = acc[tm][tn][half * 2 + 1];
                if (HAS_ADD) {
                    float2 a2 = *(const float2*)&addrow[(size_t)row * HID + col];
                    v0 += a2.x; v1 += a2.y;
                }
                if (HAS_BIAS) { v0 += __ldg(&bias[col]); v1 += __ldg(&bias[col + 1]); }
                if (STORE_RAW)
                    *(float2*)&out2[(size_t)row * HID + col] = make_float2(v0, v1);
                if (RELU) { v0 = fmaxf(v0, 0.f); v1 = fmaxf(v1, 0.f); }
                *(float2*)&out[(size_t)row * HID + col] = make_float2(v0, v1);
            }
        }
    }
}

// ---------------------------------------------------------------------------
// gather-sum over 6 padded neighbors: dst[i] = sum_j src[idx[i][j]]
// block (112, 2): one float4 column per thread.x, 2 rows per block
// ---------------------------------------------------------------------------
__global__ void gather6_sum(const float4* __restrict__ src,
                            const int* __restrict__ idx,
                            float4* __restrict__ dst, int n)
{
    int row = blockIdx.x * blockDim.y + threadIdx.y;
    if (row >= n) return;
    int c = threadIdx.x;  // 0..111
    int b[6];
    #pragma unroll
    for (int j = 0; j < 6; ++j) b[j] = __ldg(&idx[(size_t)row * 6 + j]);
    float4 acc = make_float4(0.f, 0.f, 0.f, 0.f);
    #pragma unroll
    for (int j = 0; j < 6; ++j) {
        float4 v = __ldg(&src[(size_t)b[j] * HID4 + c]);
        acc.x += v.x; acc.y += v.y; acc.z += v.z; acc.w += v.w;
    }
    dst[(size_t)row * HID4 + c] = acc;
}

// ---------------------------------------------------------------------------
// segment mean over sorted mol_idx: one block per molecule, binary-search range
// ---------------------------------------------------------------------------
__global__ void segment_mean(const float4* __restrict__ atomh,
                             const int* __restrict__ mol,
                             float4* __restrict__ out, int n_atoms)
{
    int m = blockIdx.x;
    int c = threadIdx.x;  // 0..111
    // lower_bound for m and m+1 on sorted mol[]
    int lo = 0, hi = n_atoms;
    while (lo < hi) { int mid = (lo + hi) >> 1; if (__ldg(&mol[mid]) < m) lo = mid + 1; else hi = mid; }
    int lo2 = lo, hi2 = n_atoms;
    while (lo2 < hi2) { int mid = (lo2 + hi2) >> 1; if (__ldg(&mol[mid]) < m + 1) lo2 = mid + 1; else hi2 = mid; }
    float4 acc = make_float4(0.f, 0.f, 0.f, 0.f);
    for (int a = lo; a < lo2; ++a) {
        float4 v = __ldg(&atomh[(size_t)a * HID4 + c]);
        acc.x += v.x; acc.y += v.y; acc.z += v.z; acc.w += v.w;
    }
    float inv = 1.f / fmaxf((float)(lo2 - lo), 1.f);
    out[(size_t)m * HID4 + c] = make_float4(acc.x * inv, acc.y * inv, acc.z * inv, acc.w * inv);
}

// ---------------------------------------------------------------------------
// host launcher
// ---------------------------------------------------------------------------
static void set_smem(const void* f, int bytes) {
    cudaFuncSetAttribute(f, cudaFuncAttributeMaxDynamicSharedMemorySize, bytes);
}

extern "C" void kernel_launch(void* const* d_in, const int* in_sizes, int n_in,
                              void* d_out, int out_size)
{
    const float* fatoms  = (const float*)d_in[0];
    const float* fbonds  = (const float*)d_in[1];
    const float* W_i     = (const float*)d_in[2];
    const float* W_h     = (const float*)d_in[3];
    const float* W_o     = (const float*)d_in[4];
    const float* b_o     = (const float*)d_in[5];
    const void*  agraph  = d_in[6];
    const void*  bgraph  = d_in[7];
    const void*  mol_idx = d_in[8];

    const int n_atoms = in_sizes[8];            // 80000
    const int n_bonds = in_sizes[7] / 6;        // 160001
    const int n_mols  = out_size / HID;         // 4000
    const int K_in    = in_sizes[2] / HID;      // 49
    const int K_atom  = in_sizes[0] / n_atoms;  // 38

    float *binput, *msgA, *msgB, *nei, *atomh;
    int *bgr, *agr, *mol;
    cudaGetSymbolAddress((void**)&binput, g_binput);
    cudaGetSymbolAddress((void**)&msgA,   g_msgA);
    cudaGetSymbolAddress((void**)&msgB,   g_msgB);
    cudaGetSymbolAddress((void**)&nei,    g_nei);
    cudaGetSymbolAddress((void**)&atomh,  g_atomh);
    cudaGetSymbolAddress((void**)&bgr,    g_bgraph);
    cudaGetSymbolAddress((void**)&agr,    g_agraph);
    cudaGetSymbolAddress((void**)&mol,    g_mol);

    const int SMEM = (BM * (BK + PADA) + BK * (BN + PADB)) * (int)sizeof(float2); // 54272
    set_smem((const void*)gemm3xtf32<true,  false, false, true >, SMEM);
    set_smem((const void*)gemm3xtf32<true,  true,  false, false>, SMEM);
    set_smem((const void*)gemm3xtf32<false, false, true,  false>, SMEM);

    // 0) normalize graph indices to int32 (detect int32-vs-int64 on device)
    detect_idx64<<<1, 32>>>((const unsigned int*)bgraph, 512);
    norm_idx<<<(n_bonds * 6 + 255) / 256, 256>>>(bgraph, bgr, n_bonds * 6);
    norm_idx<<<(n_atoms * 6 + 255) / 256, 256>>>(agraph, agr, n_atoms * 6);
    norm_idx<<<(n_atoms + 255) / 256, 256>>>(mol_idx, mol, n_atoms);

    dim3 blk(256);
    dim3 grdB(HID / BN, (n_bonds + BM - 1) / BM);   // (7, 1251)
    dim3 grdA(HID / BN, (n_atoms + BM - 1) / BM);   // (7, 625)
    dim3 gblk(HID4, 2);

    // 1) binput = fbonds @ W_i (raw) ; msgA = relu(binput)
    gemm3xtf32<true, false, false, true><<<grdB, blk, SMEM>>>(
        fbonds, K_in, W_i, nullptr, nullptr, msgA, binput, n_bonds, K_in);

    // 2) message-passing iterations (DEPTH-1 = 4)
    float* cur = msgA;
    float* nxt = msgB;
    for (int it = 0; it < 4; ++it) {
        gather6_sum<<<(n_bonds + 1) / 2, gblk>>>((const float4*)cur, bgr,
                                                 (float4*)nei, n_bonds);
        gemm3xtf32<true, true, false, false><<<grdB, blk, SMEM>>>(
            nei, HID, W_h, binput, nullptr, nxt, nullptr, n_bonds, HID);
        float* t = cur; cur = nxt; nxt = t;
    }

    // 3) atom readout: gather over agraph, then [fatoms | nei] @ W_o + b_o, relu
    gather6_sum<<<(n_atoms + 1) / 2, gblk>>>((const float4*)cur, agr,
                                             (float4*)nei, n_atoms);
    // atomh = fatoms @ W_o[:38] + b_o   (raw)
    gemm3xtf32<false, false, true, false><<<grdA, blk, SMEM>>>(
        fatoms, K_atom, W_o, nullptr, b_o, atomh, nullptr, n_atoms, K_atom);
    // atomh = relu(atomh + nei @ W_o[38:])
    gemm3xtf32<true, true, false, false><<<grdA, blk, SMEM>>>(
        nei, HID, W_o + (size_t)K_atom * HID, atomh, nullptr, atomh, nullptr,
        n_atoms, HID);

    // 4) per-molecule mean (sorted mol_idx, no atomics)
    segment_mean<<<n_mols, HID4>>>((const float4*)atomh, mol,
                                   (float4*)d_out, n_atoms);
}

// round 6
// speedup vs baseline: 2.2064x; 2.2064x over previous
#include <cuda_runtime.h>
#include <cuda_bf16.h>
#include <cstdint>
#include <cstddef>

// ---------------------------------------------------------------------------
// Problem constants (fixed instance)
// ---------------------------------------------------------------------------
#define NBOND_MAX 160001
#define NATOM_MAX 80000
#define HID       448
#define HID4      (HID/4)     // 112 float4 per row

// ---------------------------------------------------------------------------
// Device scratch (allocation-free rule: __device__ globals)
// ---------------------------------------------------------------------------
__device__ float g_binput[(size_t)NBOND_MAX * HID];
__device__ float g_msgA  [(size_t)NBOND_MAX * HID];
__device__ float g_msgB  [(size_t)NBOND_MAX * HID];
__device__ float g_nei   [(size_t)NBOND_MAX * HID];
__device__ float g_atomh [(size_t)NATOM_MAX * HID];

__device__ int   g_bgraph[(size_t)NBOND_MAX * 6];
__device__ int   g_agraph[(size_t)NATOM_MAX * 6];
__device__ int   g_mol   [(size_t)NATOM_MAX];
__device__ int   g_is64;

// ---------------------------------------------------------------------------
// Index dtype detection + normalization (int64 vs int32, device-side).
// ---------------------------------------------------------------------------
__global__ void detect_idx64(const unsigned int* __restrict__ words, int nwords)
{
    if (threadIdx.x == 0 && blockIdx.x == 0) {
        int is64 = 1;
        for (int i = 1; i < nwords; i += 2)
            if (words[i] != 0u) { is64 = 0; break; }
        g_is64 = is64;
    }
}

__global__ void norm_idx(const void* __restrict__ src, int* __restrict__ dst, int n)
{
    int i = blockIdx.x * blockDim.x + threadIdx.x;
    if (i >= n) return;
    if (g_is64) dst[i] = (int)((const long long*)src)[i];
    else        dst[i] = ((const int*)src)[i];
}

// ---------------------------------------------------------------------------
// 3xBF16 GEMM: C[M x 448] = A[M x K] @ W[K x 448]  (+addrow)(+bias)(relu)
// Block tile 128x64x32, 256 threads, warp tile 32x32 (2x4 m16n8k16 mma tiles).
// Each fp32 split into (bf16_hi, bf16_lo); 3 products hi*hi + hi*lo + lo*hi.
// Double-buffered smem + register prefetch: 1 syncthreads per K-tile.
// ---------------------------------------------------------------------------
#define BM 128
#define BN 64
#define BK 32
#define ASTR 40                 // bf16 row stride for A  [m][k]  (BK+8)
#define BSTR 40                 // bf16 row stride for B^T [n][k] (BK+8)
#define A_SZ (BM * ASTR)        // 5120 bf16
#define B_SZ (BN * BSTR)        // 2560 bf16
#define BUF_SZ (2 * A_SZ + 2 * B_SZ)   // hi+lo for A and B: 15360 bf16
#define GEMM_SMEM (2 * BUF_SZ * 2)     // 2 buffers * bytes = 61440

__device__ __forceinline__ void mma_bf16(float* d, const uint32_t* a, const uint32_t* b) {
    asm volatile(
        "mma.sync.aligned.m16n8k16.row.col.f32.bf16.bf16.f32 "
        "{%0,%1,%2,%3}, {%4,%5,%6,%7}, {%8,%9}, {%0,%1,%2,%3};\n"
        : "+f"(d[0]), "+f"(d[1]), "+f"(d[2]), "+f"(d[3])
        : "r"(a[0]), "r"(a[1]), "r"(a[2]), "r"(a[3]), "r"(b[0]), "r"(b[1]));
}

__device__ __forceinline__ void split_bf16(float v, __nv_bfloat16& hi, __nv_bfloat16& lo) {
    hi = __float2bfloat16(v);
    lo = __float2bfloat16(v - __bfloat162float(hi));
}

template<bool RELU, bool HAS_ADD, bool HAS_BIAS, bool STORE_RAW>
__global__ void __launch_bounds__(256)
gemm_bf16x3(const float* __restrict__ A, int lda,
            const float* __restrict__ W,                 // [K x 448], ldb = 448
            const float* __restrict__ addrow,            // [M x 448] or null
            const float* __restrict__ bias,              // [448] or null
            float* __restrict__ out,                     // [M x 448]
            float* __restrict__ out2,                    // raw (pre-relu) store
            int M, int K)
{
    extern __shared__ __nv_bfloat16 smem[];

    const int tid  = threadIdx.x;
    const int m0   = blockIdx.y * BM;
    const int n0   = blockIdx.x * BN;
    const int warp = tid >> 5, lane = tid & 31;
    const int wm   = (warp & 3) * 32;      // 4 warps along M
    const int wn   = (warp >> 2) * 32;     // 2 warps along N
    const int g    = lane >> 2, tig = lane & 3;

    float acc[2][4][4] = {};
    float rA[16];          // A tile fragment: 128x32 / 256 thr
    float rB[8];           // B tile fragment: 32x64 / 256 thr (k-pairs)

    const int nk = (K + BK - 1) / BK;

    // gmem tile load into registers (bounds-checked)
    auto load_tile = [&](int kt) {
        const int k0 = kt * BK;
        #pragma unroll
        for (int i = 0; i < 16; ++i) {
            int idx = tid + i * 256;
            int r = idx >> 5, c = idx & 31;
            int gr = m0 + r, gc = k0 + c;
            rA[i] = (gr < M && gc < K) ? __ldg(&A[(size_t)gr * lda + gc]) : 0.f;
        }
        #pragma unroll
        for (int i = 0; i < 4; ++i) {
            int idx = tid + i * 256;          // 1024 k-pairs
            int n = idx & 63, k2 = idx >> 6;  // k2 in 0..15
            int gk0 = k0 + 2 * k2;
            rB[2 * i]     = (gk0     < K) ? __ldg(&W[(size_t)gk0       * HID + n0 + n]) : 0.f;
            rB[2 * i + 1] = (gk0 + 1 < K) ? __ldg(&W[(size_t)(gk0 + 1) * HID + n0 + n]) : 0.f;
        }
    };

    // split + store register tile into smem buffer p
    auto store_tile = [&](int p) {
        __nv_bfloat16* sAhi = smem + p * BUF_SZ;
        __nv_bfloat16* sAlo = sAhi + A_SZ;
        __nv_bfloat16* sBhi = sAlo + A_SZ;
        __nv_bfloat16* sBlo = sBhi + B_SZ;
        #pragma unroll
        for (int i = 0; i < 16; ++i) {
            int idx = tid + i * 256;
            int r = idx >> 5, c = idx & 31;
            __nv_bfloat16 h, l;
            split_bf16(rA[i], h, l);
            sAhi[r * ASTR + c] = h;
            sAlo[r * ASTR + c] = l;
        }
        #pragma unroll
        for (int i = 0; i < 4; ++i) {
            int idx = tid + i * 256;
            int n = idx & 63, k2 = idx >> 6;
            __nv_bfloat16 h0, l0, h1, l1;
            split_bf16(rB[2 * i],     h0, l0);
            split_bf16(rB[2 * i + 1], h1, l1);
            // pack (k, k+1) pair as one 32-bit word (low half = even k)
            __nv_bfloat162 ph = __halves2bfloat162(h0, h1);
            __nv_bfloat162 pl = __halves2bfloat162(l0, l1);
            *(__nv_bfloat162*)&sBhi[n * BSTR + 2 * k2] = ph;
            *(__nv_bfloat162*)&sBlo[n * BSTR + 2 * k2] = pl;
        }
    };

    load_tile(0);
    int p = 0;
    for (int kt = 0; kt < nk; ++kt) {
        store_tile(p);
        __syncthreads();
        if (kt + 1 < nk) load_tile(kt + 1);   // LDGs overlap with mma below

        const __nv_bfloat16* sAhi = smem + p * BUF_SZ;
        const __nv_bfloat16* sAlo = sAhi + A_SZ;
        const __nv_bfloat16* sBhi = sAlo + A_SZ;
        const __nv_bfloat16* sBlo = sBhi + B_SZ;

        #pragma unroll
        for (int half = 0; half < 2; ++half) {
            const int k0 = half * 16;
            uint32_t ah[2][4], al[2][4], bh[4][2], bl[4][2];
            #pragma unroll
            for (int tm = 0; tm < 2; ++tm) {
                int r = wm + tm * 16 + g;
                const __nv_bfloat16* ph = sAhi + r * ASTR + k0 + 2 * tig;
                const __nv_bfloat16* pl = sAlo + r * ASTR + k0 + 2 * tig;
                ah[tm][0] = *(const uint32_t*)(ph);
                ah[tm][1] = *(const uint32_t*)(ph + 8 * ASTR);
                ah[tm][2] = *(const uint32_t*)(ph + 8);
                ah[tm][3] = *(const uint32_t*)(ph + 8 * ASTR + 8);
                al[tm][0] = *(const uint32_t*)(pl);
                al[tm][1] = *(const uint32_t*)(pl + 8 * ASTR);
                al[tm][2] = *(const uint32_t*)(pl + 8);
                al[tm][3] = *(const uint32_t*)(pl + 8 * ASTR + 8);
            }
            #pragma unroll
            for (int tn = 0; tn < 4; ++tn) {
                int n = wn + tn * 8 + g;
                const __nv_bfloat16* ph = sBhi + n * BSTR + k0 + 2 * tig;
                const __nv_bfloat16* pl = sBlo + n * BSTR + k0 + 2 * tig;
                bh[tn][0] = *(const uint32_t*)(ph);
                bh[tn][1] = *(const uint32_t*)(ph + 8);
                bl[tn][0] = *(const uint32_t*)(pl);
                bl[tn][1] = *(const uint32_t*)(pl + 8);
            }
            #pragma unroll
            for (int tm = 0; tm < 2; ++tm)
                #pragma unroll
                for (int tn = 0; tn < 4; ++tn) {
                    mma_bf16(acc[tm][tn], ah[tm], bh[tn]);
                    mma_bf16(acc[tm][tn], ah[tm], bl[tn]);
                    mma_bf16(acc[tm][tn], al[tm], bh[tn]);
                }
        }
        p ^= 1;
    }

    // --- epilogue: (c0,c1)/(c2,c3) are col pairs at rows r / r+8 ---
    #pragma unroll
    for (int tm = 0; tm < 2; ++tm) {
        #pragma unroll
        for (int half = 0; half < 2; ++half) {
            int row = m0 + wm + tm * 16 + g + half * 8;
            if (row >= M) continue;
            #pragma unroll
            for (int tn = 0; tn < 4; ++tn) {
                int col = n0 + wn + tn * 8 + 2 * tig;
                float v0 = acc[tm][tn][half * 2 + 0];
                float v1 = acc[tm][tn][half * 2 + 1];
                if (HAS_ADD) {
                    float2 a2 = *(const float2*)&addrow[(size_t)row * HID + col];
                    v0 += a2.x; v1 += a2.y;
                }
                if (HAS_BIAS) { v0 += __ldg(&bias[col]); v1 += __ldg(&bias[col + 1]); }
                if (STORE_RAW)
                    *(float2*)&out2[(size_t)row * HID + col] = make_float2(v0, v1);
                if (RELU) { v0 = fmaxf(v0, 0.f); v1 = fmaxf(v1, 0.f); }
                *(float2*)&out[(size_t)row * HID + col] = make_float2(v0, v1);
            }
        }
    }
}

// ---------------------------------------------------------------------------
// gather-sum over 6 padded neighbors: dst[i] = sum_j src[idx[i][j]]
// ---------------------------------------------------------------------------
__global__ void gather6_sum(const float4* __restrict__ src,
                            const int* __restrict__ idx,
                            float4* __restrict__ dst, int n)
{
    int row = blockIdx.x * blockDim.y + threadIdx.y;
    if (row >= n) return;
    int c = threadIdx.x;  // 0..111
    int b[6];
    #pragma unroll
    for (int j = 0; j < 6; ++j) b[j] = __ldg(&idx[(size_t)row * 6 + j]);
    float4 acc = make_float4(0.f, 0.f, 0.f, 0.f);
    #pragma unroll
    for (int j = 0; j < 6; ++j) {
        float4 v = __ldg(&src[(size_t)b[j] * HID4 + c]);
        acc.x += v.x; acc.y += v.y; acc.z += v.z; acc.w += v.w;
    }
    dst[(size_t)row * HID4 + c] = acc;
}

// ---------------------------------------------------------------------------
// segment mean over sorted mol_idx: one block per molecule, binary-search range
// ---------------------------------------------------------------------------
__global__ void segment_mean(const float4* __restrict__ atomh,
                             const int* __restrict__ mol,
                             float4* __restrict__ out, int n_atoms)
{
    int m = blockIdx.x;
    int c = threadIdx.x;  // 0..111
    int lo = 0, hi = n_atoms;
    while (lo < hi) { int mid = (lo + hi) >> 1; if (__ldg(&mol[mid]) < m) lo = mid + 1; else hi = mid; }
    int lo2 = lo, hi2 = n_atoms;
    while (lo2 < hi2) { int mid = (lo2 + hi2) >> 1; if (__ldg(&mol[mid]) < m + 1) lo2 = mid + 1; else hi2 = mid; }
    float4 acc = make_float4(0.f, 0.f, 0.f, 0.f);
    for (int a = lo; a < lo2; ++a) {
        float4 v = __ldg(&atomh[(size_t)a * HID4 + c]);
        acc.x += v.x; acc.y += v.y; acc.z += v.z; acc.w += v.w;
    }
    float inv = 1.f / fmaxf((float)(lo2 - lo), 1.f);
    out[(size_t)m * HID4 + c] = make_float4(acc.x * inv, acc.y * inv, acc.z * inv, acc.w * inv);
}

// ---------------------------------------------------------------------------
// host launcher
// ---------------------------------------------------------------------------
static void set_smem(const void* f, int bytes) {
    cudaFuncSetAttribute(f, cudaFuncAttributeMaxDynamicSharedMemorySize, bytes);
}

extern "C" void kernel_launch(void* const* d_in, const int* in_sizes, int n_in,
                              void* d_out, int out_size)
{
    const float* fatoms  = (const float*)d_in[0];
    const float* fbonds  = (const float*)d_in[1];
    const float* W_i     = (const float*)d_in[2];
    const float* W_h     = (const float*)d_in[3];
    const float* W_o     = (const float*)d_in[4];
    const float* b_o     = (const float*)d_in[5];
    const void*  agraph  = d_in[6];
    const void*  bgraph  = d_in[7];
    const void*  mol_idx = d_in[8];

    const int n_atoms = in_sizes[8];            // 80000
    const int n_bonds = in_sizes[7] / 6;        // 160001
    const int n_mols  = out_size / HID;         // 4000
    const int K_in    = in_sizes[2] / HID;      // 49
    const int K_atom  = in_sizes[0] / n_atoms;  // 38

    float *binput, *msgA, *msgB, *nei, *atomh;
    int *bgr, *agr, *mol;
    cudaGetSymbolAddress((void**)&binput, g_binput);
    cudaGetSymbolAddress((void**)&msgA,   g_msgA);
    cudaGetSymbolAddress((void**)&msgB,   g_msgB);
    cudaGetSymbolAddress((void**)&nei,    g_nei);
    cudaGetSymbolAddress((void**)&atomh,  g_atomh);
    cudaGetSymbolAddress((void**)&bgr,    g_bgraph);
    cudaGetSymbolAddress((void**)&agr,    g_agraph);
    cudaGetSymbolAddress((void**)&mol,    g_mol);

    set_smem((const void*)gemm_bf16x3<true,  false, false, true >, GEMM_SMEM);
    set_smem((const void*)gemm_bf16x3<true,  true,  false, false>, GEMM_SMEM);
    set_smem((const void*)gemm_bf16x3<false, false, true,  false>, GEMM_SMEM);

    // 0) normalize graph indices to int32 (detect int32-vs-int64 on device)
    detect_idx64<<<1, 32>>>((const unsigned int*)bgraph, 512);
    norm_idx<<<(n_bonds * 6 + 255) / 256, 256>>>(bgraph, bgr, n_bonds * 6);
    norm_idx<<<(n_atoms * 6 + 255) / 256, 256>>>(agraph, agr, n_atoms * 6);
    norm_idx<<<(n_atoms + 255) / 256, 256>>>(mol_idx, mol, n_atoms);

    dim3 blk(256);
    dim3 grdB(HID / BN, (n_bonds + BM - 1) / BM);   // (7, 1251)
    dim3 grdA(HID / BN, (n_atoms + BM - 1) / BM);   // (7, 625)
    dim3 gblk(HID4, 2);

    // 1) binput = fbonds @ W_i (raw) ; msgA = relu(binput)
    gemm_bf16x3<true, false, false, true><<<grdB, blk, GEMM_SMEM>>>(
        fbonds, K_in, W_i, nullptr, nullptr, msgA, binput, n_bonds, K_in);

    // 2) message-passing iterations (DEPTH-1 = 4)
    float* cur = msgA;
    float* nxt = msgB;
    for (int it = 0; it < 4; ++it) {
        gather6_sum<<<(n_bonds + 1) / 2, gblk>>>((const float4*)cur, bgr,
                                                 (float4*)nei, n_bonds);
        gemm_bf16x3<true, true, false, false><<<grdB, blk, GEMM_SMEM>>>(
            nei, HID, W_h, binput, nullptr, nxt, nullptr, n_bonds, HID);
        float* t = cur; cur = nxt; nxt = t;
    }

    // 3) atom readout: gather over agraph, then [fatoms | nei] @ W_o + b_o, relu
    gather6_sum<<<(n_atoms + 1) / 2, gblk>>>((const float4*)cur, agr,
                                             (float4*)nei, n_atoms);
    // atomh = fatoms @ W_o[:38] + b_o   (raw)
    gemm_bf16x3<false, false, true, false><<<grdA, blk, GEMM_SMEM>>>(
        fatoms, K_atom, W_o, nullptr, b_o, atomh, nullptr, n_atoms, K_atom);
    // atomh = relu(atomh + nei @ W_o[38:])
    gemm_bf16x3<true, true, false, false><<<grdA, blk, GEMM_SMEM>>>(
        nei, HID, W_o + (size_t)K_atom * HID, atomh, nullptr, atomh, nullptr,
        n_atoms, HID);

    // 4) per-molecule mean (sorted mol_idx, no atomics)
    segment_mean<<<n_mols, HID4>>>((const float4*)atomh, mol,
                                   (float4*)d_out, n_atoms);
}